// round 14
// baseline (speedup 1.0000x reference)
#include <cuda_runtime.h>
#include <cstdint>

// ---------------- problem constants ----------------
#define B_    8
#define HW_   4096
#define HDIM_ 64
#define C_    1024
#define M_    32
#define P_    512

// ---------------- GEMM tiling ----------------
#define CTILE   256                 // channels per CTA
#define NBLKS   (C_ / CTILE)        // 4
#define KSPLIT  8                   // K split across grid.z
#define KRANGE  (HW_ / KSPLIT)      // 512 k per CTA
#define KC      16                  // k (pixels) per chunk
#define NCHUNK  (KRANGE / KC)       // 32 chunks per CTA
#define NCTAS   (NBLKS * B_ * KSPLIT)   // 256 == B_*M_

// ---- smem layout ----
// Per-warp F ring: 2 stages x [16 k x 40 words] (stride 40 -> banks 8c+r, CF)
#define FSTW   40
#define FSTAGEB (KC * FSTW * 4)     // 2560 B per warp-stage
#define FRINGB  (2 * 8 * FSTAGEB)   // 40960 B total
// Persistent W: [32 m][512 k + 4 pad] stride 516 words -> banks 4r+c, CF
#define WSW    516
#define WROWB  (WSW * 4)            // 2064
#define WBASE  FRINGB               // 40960
#define WBYTES (M_ * WROWB)         // 66048
#define SMEM_TOTAL (WBASE + WBYTES) // 107008 -> 2 CTAs/SM

// epilogue staging tile: [32 m][260 words]
#define ESW 260

// Scratch: tf32(RNA)-rounded weights; device-wide barrier (self-resetting)
__device__ float g_W[(size_t)B_ * M_ * HW_];
__device__ unsigned int g_bar;
__device__ unsigned int g_bar2;

// ---------------- helpers ----------------
__device__ __forceinline__ uint32_t smem_u32(const void* p) {
    uint32_t a;
    asm("{ .reg .u64 t; cvta.to.shared.u64 t, %1; cvt.u32.u64 %0, t; }" : "=r"(a) : "l"(p));
    return a;
}
__device__ __forceinline__ void cp_async16(uint32_t dst, const void* src) {
    asm volatile("cp.async.cg.shared.global [%0], [%1], 16;" :: "r"(dst), "l"(src));
}
#define CP_COMMIT() asm volatile("cp.async.commit_group;" ::: "memory")
#define CP_WAIT0()  asm volatile("cp.async.wait_group 0;" ::: "memory")
#define CP_WAIT1()  asm volatile("cp.async.wait_group 1;" ::: "memory")

__device__ __forceinline__ uint32_t to_tf32(float x) {
    uint32_t r;
    asm("cvt.rna.tf32.f32 %0, %1;" : "=r"(r) : "f"(x));
    return r;
}
__device__ __forceinline__ void red_add_v4(float* gptr, float4 v) {
    asm volatile("red.global.add.v4.f32 [%0], {%1, %2, %3, %4};"
                 :: "l"(gptr), "f"(v.x), "f"(v.y), "f"(v.z), "f"(v.w) : "memory");
}

// D[16ch x 8m] += A[16ch x 8k] * B[8k x 8m]   (tf32, fp32 accum)
__device__ __forceinline__ void mma_tf32(float* d,
                                         uint32_t a0, uint32_t a1, uint32_t a2, uint32_t a3,
                                         uint32_t b0, uint32_t b1) {
    asm volatile(
        "mma.sync.aligned.m16n8k8.row.col.f32.tf32.tf32.f32 "
        "{%0,%1,%2,%3}, {%4,%5,%6,%7}, {%8,%9}, {%0,%1,%2,%3};"
        : "+f"(d[0]), "+f"(d[1]), "+f"(d[2]), "+f"(d[3])
        : "r"(a0), "r"(a1), "r"(a2), "r"(a3), "r"(b0), "r"(b1));
}

// ---------------------------------------------------------------------------
// Single fused kernel, per-warp self-paced pipeline:
//  per-warp F0,F1 prefetch -> phase A (histogram) -> device barrier ->
//  persistent W load (once) -> mainloop with NO __syncthreads and per-warp
//  cp.async pacing -> REDG v4 epilogue.
// ---------------------------------------------------------------------------
__global__ void __launch_bounds__(256, 2) fused_mma(
    const float* __restrict__ coords,   // [B, M, P, 2]
    const float* __restrict__ F,        // [B, HW, C]
    float* __restrict__ out)            // [B, M, 1, C]
{
    extern __shared__ char smem[];
    const uint32_t sbase = smem_u32(smem);
    float* wsm = reinterpret_cast<float*>(smem + WBASE);

    const int tid  = threadIdx.x;
    const int lane = tid & 31;
    const int wid  = tid >> 5;          // 0..7
    const int nblk = blockIdx.x;        // 0..3
    const int b    = blockIdx.y;        // 0..7
    const int ksp  = blockIdx.z;        // 0..7
    const int c0   = nblk * CTILE;
    const int kbase = ksp * KRANGE;

    const int r = lane >> 2;            // 0..7
    const int c = lane & 3;             // 0..3
    const int chw = wid * 32;           // warp channel base within tile

    // ---- per-warp F loader: warp w loads its own [16k x 32ch] slice ----
    const int lrow = lane >> 3;         // 0..3 (k-row subgroup)
    const int lu   = lane & 7;          // 16B unit within 128B row segment
    const float* fwp = F + ((size_t)b * HW_ + kbase) * C_ + c0 + chw + lu * 4;

    auto load_F = [&](int i) {          // local chunk i -> stage i&1
        const int k0 = i * KC;
        const uint32_t fb = sbase + (uint32_t)(((i & 1) * 8 + wid) * FSTAGEB);
        #pragma unroll
        for (int h = 0; h < 4; h++) {
            int row = h * 4 + lrow;     // 0..15
            cp_async16(fb + (uint32_t)(row * (FSTW * 4) + lu * 16),
                       fwp + (size_t)(k0 + row) * C_);
        }
    };

    // ---- per-warp F prefetch for chunks 0,1 (independent of weights) ----
    load_F(0); CP_COMMIT();
    load_F(1); CP_COMMIT();

    // ---- Phase A: histogram for (b,m)=flat + zero this CTA's out slice ----
    {
        const int flat = nblk + NBLKS * (b + B_ * ksp);   // bijection 0..255
        float4* oz = reinterpret_cast<float4*>(out + (size_t)flat * 1024);
        oz[tid] = make_float4(0.f, 0.f, 0.f, 0.f);

        float* hist = wsm;              // 16KB inside W area (W loads later)
        #pragma unroll 4
        for (int i = tid; i < HW_; i += 256) hist[i] = 0.0f;
        __syncthreads();

        const float* cp = coords + (size_t)flat * P_ * 2;
        const float invP = 1.0f / (float)P_;
        const float s = (float)(HDIM_ - 1);

        for (int p = tid; p < P_; p += 256) {
            float yn = cp[p * 2 + 0];
            float xn = cp[p * 2 + 1];
            float y = yn * s;
            float x = xn * s;
            float x0f = floorf(x), y0f = floorf(y);
            float wx = x - x0f, wy = y - y0f;
            int ix0 = min(max((int)x0f, 0), HDIM_ - 1);
            int ix1 = min(ix0 + 1, HDIM_ - 1);
            int iy0 = min(max((int)y0f, 0), HDIM_ - 1);
            int iy1 = min(iy0 + 1, HDIM_ - 1);
            atomicAdd(&hist[iy0 * HDIM_ + ix0], (1.0f - wx) * (1.0f - wy) * invP);
            atomicAdd(&hist[iy0 * HDIM_ + ix1], wx * (1.0f - wy) * invP);
            atomicAdd(&hist[iy1 * HDIM_ + ix0], (1.0f - wx) * wy * invP);
            atomicAdd(&hist[iy1 * HDIM_ + ix1], wx * wy * invP);
        }
        __syncthreads();

        float* wout = g_W + (size_t)flat * HW_;
        #pragma unroll 4
        for (int i = tid; i < HW_; i += 256)
            wout[i] = __uint_as_float(to_tf32(hist[i]));
    }

    // ---- Device-wide barrier (single wave: all 256 CTAs co-resident) ----
    __threadfence();
    __syncthreads();
    if (tid == 0) {
        atomicAdd(&g_bar, 1u);
        while (*((volatile unsigned int*)&g_bar) < NCTAS) {}
    }
    __syncthreads();
    __threadfence();    // acquire all g_W writes + out zeroing

    // ---- Load FULL W range [32m x 512k] into persistent smem (once) ----
    {
        const float* WbK = g_W + (size_t)b * M_ * HW_ + kbase;
        #pragma unroll
        for (int h = 0; h < 16; h++) {
            int u  = tid + h * 256;     // 0..4095 16B units
            int m  = u >> 7;            // 128 units per m-row
            int ku = u & 127;
            cp_async16(sbase + WBASE + (uint32_t)(m * WROWB + ku * 16),
                       WbK + (size_t)m * HW_ + ku * 4);
        }
        CP_COMMIT();
    }
    CP_WAIT0();                 // W resident (also F0, F1 — loaded during phase A)
    __syncthreads();

    float d[2][4][4];
    #pragma unroll
    for (int t = 0; t < 2; t++)
        #pragma unroll
        for (int j = 0; j < 4; j++)
            #pragma unroll
            for (int e = 0; e < 4; e++) d[t][j][e] = 0.f;

    // ---- mainloop: per-warp self-paced, NO __syncthreads ----
    for (int i = 0; i < NCHUNK; i++) {
        CP_WAIT1();             // this warp's chunk i resident

        const float* fs = reinterpret_cast<const float*>(
            smem + ((i & 1) * 8 + wid) * FSTAGEB);

        #pragma unroll
        for (int ks = 0; ks < KC / 8; ks++) {
            const int kr = ks * 8;
            uint32_t a[2][4];
            #pragma unroll
            for (int t = 0; t < 2; t++) {
                a[t][0] = to_tf32(fs[(kr + c) * FSTW + t * 16 + r]);
                a[t][1] = to_tf32(fs[(kr + c) * FSTW + t * 16 + r + 8]);
                a[t][2] = to_tf32(fs[(kr + c + 4) * FSTW + t * 16 + r]);
                a[t][3] = to_tf32(fs[(kr + c + 4) * FSTW + t * 16 + r + 8]);
            }
            const int kk = i * KC + kr;
            uint32_t bf[4][2];
            #pragma unroll
            for (int j = 0; j < 4; j++) {
                bf[j][0] = __float_as_uint(wsm[(j * 8 + r) * WSW + kk + c]);
                bf[j][1] = __float_as_uint(wsm[(j * 8 + r) * WSW + kk + c + 4]);
            }
            #pragma unroll
            for (int t = 0; t < 2; t++)
                #pragma unroll
                for (int j = 0; j < 4; j++)
                    mma_tf32(d[t][j], a[t][0], a[t][1], a[t][2], a[t][3],
                             bf[j][0], bf[j][1]);
        }

        if (i + 2 < NCHUNK) load_F(i + 2);   // refill stage i&1 (reads above done)
        CP_COMMIT();            // one group per iteration (may be empty)
    }

    // ---- epilogue: stage D[32m x 256ch] in smem (reuse all), REDG v4 ----
    __syncthreads();            // all warps done with rings + W
    {
        float* etile = reinterpret_cast<float*>(smem);      // [32][ESW]
        #pragma unroll
        for (int t = 0; t < 2; t++) {
            const int ch = chw + t * 16 + r;
            #pragma unroll
            for (int j = 0; j < 4; j++) {
                int mA = j * 8 + 2 * c, mB = mA + 1;
                etile[mA * ESW + ch]     = d[t][j][0];
                etile[mB * ESW + ch]     = d[t][j][1];
                etile[mA * ESW + ch + 8] = d[t][j][2];
                etile[mB * ESW + ch + 8] = d[t][j][3];
            }
        }
        __syncthreads();

        float* ob = out + (size_t)b * M_ * C_ + c0;
        #pragma unroll
        for (int h = 0; h < 8; h++) {
            int idx = tid + h * 256;        // 0..2047
            int m = idx >> 6;               // 0..31
            int q = idx & 63;               // float4 slot within 256 ch
            const float4 v = *reinterpret_cast<const float4*>(etile + m * ESW + q * 4);
            red_add_v4(ob + (size_t)m * C_ + q * 4, v);
        }
    }

    // ---- barrier self-reset ----
    __syncthreads();
    if (tid == 0) {
        unsigned int old = atomicAdd(&g_bar2, 1u);
        if (old == NCTAS - 1) {
            g_bar = 0;
            g_bar2 = 0;
            __threadfence();
        }
    }
}

// ---------------------------------------------------------------------------
extern "C" void kernel_launch(void* const* d_in, const int* in_sizes, int n_in,
                              void* d_out, int out_size)
{
    const float* feature = (const float*)d_in[0];
    const float* coords  = (const float*)d_in[1];
    if (n_in >= 2 && in_sizes[0] == B_ * M_ * P_ * 2) {
        feature = (const float*)d_in[1];
        coords  = (const float*)d_in[0];
    }

    cudaFuncSetAttribute(fused_mma, cudaFuncAttributeMaxDynamicSharedMemorySize, SMEM_TOTAL);

    dim3 g2(NBLKS, B_, KSPLIT);
    fused_mma<<<g2, 256, SMEM_TOTAL>>>(coords, feature, (float*)d_out);
}